// round 1
// baseline (speedup 1.0000x reference)
#include <cuda_runtime.h>
#include <math.h>

// ---------------- problem constants ----------------
#define BN   8
#define TT   1024
#define CCH  768
#define HH   12
#define HSZ  64
#define EE   8
#define FF   3072
#define NT   (BN*TT)        // 8192 tokens
#define BH   (BN*HH)        // 96

// ---------------- static scratch (no allocs allowed) ----------------
__device__ float g_h1[NT*CCH];
__device__ float g_q [BH*TT*HSZ];
__device__ float g_k [BH*TT*HSZ];
__device__ float g_v [BH*TT*HSZ];
__device__ float g_S [(size_t)BH*TT*TT];    // 402 MB attention scores/probs
__device__ float g_ao[NT*CCH];
__device__ float g_x2[NT*CCH];
__device__ float g_h2[NT*CCH];
__device__ float g_gw[NT*2];
__device__ int   g_pos[NT*2];
__device__ int   g_tok[EE*NT];
__device__ int   g_cnt[EE];
__device__ float g_t1[NT*FF];
__device__ float g_t2[NT*FF];
__device__ float g_t3[NT*CCH];
__device__ float g_ob[(size_t)EE*NT*CCH];   // expert outputs by global slot

__device__ __forceinline__ float geluf(float v){
    return 0.5f*v*(1.f + erff(v*0.70710678118654752440f));
}

// ---------------- reset per-replay state ----------------
__global__ void k_reset(){ if(threadIdx.x < EE) g_cnt[threadIdx.x] = 0; }

// ---------------- row LayerNorm: out = LN(in)*g+b, rows of 768 ----------------
__global__ void k_ln(const float* __restrict__ in, const float* __restrict__ gam,
                     const float* __restrict__ bet, float* __restrict__ out){
    int n = blockIdx.x, t = threadIdx.x;
    const float* row = in + (size_t)n*CCH;
    float v[3], s = 0.f, s2 = 0.f;
#pragma unroll
    for(int i=0;i<3;i++){ v[i]=row[t+256*i]; s+=v[i]; s2+=v[i]*v[i]; }
    __shared__ float shs[8], shq[8];
#pragma unroll
    for(int o=16;o;o>>=1){ s+=__shfl_xor_sync(~0u,s,o); s2+=__shfl_xor_sync(~0u,s2,o); }
    if((t&31)==0){ shs[t>>5]=s; shq[t>>5]=s2; }
    __syncthreads();
    s=0.f; s2=0.f;
#pragma unroll
    for(int i=0;i<8;i++){ s+=shs[i]; s2+=shq[i]; }
    float mean = s*(1.f/768.f);
    float var  = s2*(1.f/768.f) - mean*mean;
    float r = rsqrtf(var + 1e-5f);
#pragma unroll
    for(int i=0;i<3;i++){
        int c = t+256*i;
        out[(size_t)n*CCH+c] = (v[i]-mean)*r*gam[c] + bet[c];
    }
}

// ---------------- QKV projection: per (b,h,{q,k,v}) 64x64 tiles ----------------
__global__ void k_qkv(const float* __restrict__ h1, const float* __restrict__ wq,
                      const float* __restrict__ wk, const float* __restrict__ wv){
    int tb = blockIdx.x, bh = blockIdx.y, which = blockIdx.z;
    int b = bh / HH, h = bh % HH;
    const float* W = (which==0? wq : which==1? wk : wv) + (size_t)h*CCH*HSZ;
    float* O = (which==0? g_q : which==1? g_k : g_v) + (size_t)bh*TT*HSZ;
    __shared__ float As[16][68];
    __shared__ float Bs[16][64];
    int tid = threadIdx.x, ty = tid>>4, tx = tid&15;
    int arow = tid>>2, akq = (tid&3)*4;
    const float* Ap = h1 + ((size_t)b*TT + tb*64 + arow)*CCH;
    int brow = tid>>4, bd = (tid&15)*4;
    float acc[4][4] = {};
    for(int k0=0;k0<CCH;k0+=16){
        float4 av = *(const float4*)(Ap + k0 + akq);
        As[akq+0][arow]=av.x; As[akq+1][arow]=av.y; As[akq+2][arow]=av.z; As[akq+3][arow]=av.w;
        *(float4*)&Bs[brow][bd] = *(const float4*)(W + (size_t)(k0+brow)*HSZ + bd);
        __syncthreads();
#pragma unroll
        for(int kk=0;kk<16;kk++){
            float a[4], bb[4];
#pragma unroll
            for(int i=0;i<4;i++) a[i]=As[kk][ty*4+i];
#pragma unroll
            for(int j=0;j<4;j++) bb[j]=Bs[kk][tx*4+j];
#pragma unroll
            for(int i=0;i<4;i++)
#pragma unroll
                for(int j=0;j<4;j++) acc[i][j]+=a[i]*bb[j];
        }
        __syncthreads();
    }
#pragma unroll
    for(int i=0;i<4;i++)
#pragma unroll
        for(int j=0;j<4;j++)
            O[(size_t)(tb*64+ty*4+i)*HSZ + tx*4+j] = acc[i][j];
}

// ---------------- scores: S = scale * Q K^T with causal mask ----------------
__global__ void k_scores(){
    int sb = blockIdx.x, tb = blockIdx.y, bh = blockIdx.z;
    if(sb > tb) return;                // strictly-upper tiles never read (softmax zeros tail)
    __shared__ float Qs[64][65];       // [d][t]
    __shared__ float Ks[64][65];       // [d][s]
    const float* Q = g_q + (size_t)bh*TT*HSZ + (size_t)tb*64*HSZ;
    const float* K = g_k + (size_t)bh*TT*HSZ + (size_t)sb*64*HSZ;
    int tid = threadIdx.x;
#pragma unroll
    for(int i=0;i<4;i++){
        int idx = tid + i*256;
        int r = idx>>4, d4 = (idx&15)*4;
        float4 qv = *(const float4*)(Q + r*HSZ + d4);
        Qs[d4+0][r]=qv.x; Qs[d4+1][r]=qv.y; Qs[d4+2][r]=qv.z; Qs[d4+3][r]=qv.w;
        float4 kv = *(const float4*)(K + r*HSZ + d4);
        Ks[d4+0][r]=kv.x; Ks[d4+1][r]=kv.y; Ks[d4+2][r]=kv.z; Ks[d4+3][r]=kv.w;
    }
    __syncthreads();
    int ty = tid>>4, tx = tid&15;
    float acc[4][4] = {};
#pragma unroll
    for(int k=0;k<64;k++){
        float a[4], bb[4];
#pragma unroll
        for(int i=0;i<4;i++) a[i]=Qs[k][ty*4+i];
#pragma unroll
        for(int j=0;j<4;j++) bb[j]=Ks[k][tx*4+j];
#pragma unroll
        for(int i=0;i<4;i++)
#pragma unroll
            for(int j=0;j<4;j++) acc[i][j]+=a[i]*bb[j];
    }
    const float scale = 0.036084391824351615f;  // 768^-0.5
    float* S = g_S + (size_t)bh*TT*TT;
#pragma unroll
    for(int i=0;i<4;i++){
        int tg = tb*64+ty*4+i;
#pragma unroll
        for(int j=0;j<4;j++){
            int sg = sb*64+tx*4+j;
            S[(size_t)tg*TT + sg] = (sg<=tg) ? acc[i][j]*scale : -1e30f;
        }
    }
}

// ---------------- row softmax over [0,t], zero tail ----------------
__global__ void k_softmax(){
    int row = blockIdx.x;
    int bh = row>>10, t = row & (TT-1);
    float* S = g_S + (size_t)bh*TT*TT + (size_t)t*TT;
    int len = t+1, tid = threadIdx.x;
    __shared__ float sh[8];
    float m = -1e30f;
    for(int s=tid;s<len;s+=256) m = fmaxf(m, S[s]);
#pragma unroll
    for(int o=16;o;o>>=1) m = fmaxf(m, __shfl_xor_sync(~0u,m,o));
    if((tid&31)==0) sh[tid>>5]=m;
    __syncthreads();
    m = sh[0];
#pragma unroll
    for(int i=1;i<8;i++) m = fmaxf(m, sh[i]);
    __syncthreads();
    float sum = 0.f;
    for(int s=tid;s<len;s+=256){ float e = expf(S[s]-m); S[s]=e; sum+=e; }
#pragma unroll
    for(int o=16;o;o>>=1) sum += __shfl_xor_sync(~0u,sum,o);
    if((tid&31)==0) sh[tid>>5]=sum;
    __syncthreads();
    sum = 0.f;
#pragma unroll
    for(int i=0;i<8;i++) sum += sh[i];
    float inv = 1.f/sum;
    for(int s=tid;s<TT;s+=256) S[s] = (s<len) ? S[s]*inv : 0.f;
}

// ---------------- O = P @ V, write to [b,t,h*HS+d] ----------------
__global__ void k_av(){
    int tb = blockIdx.x, bh = blockIdx.y;
    const float* P = g_S + (size_t)bh*TT*TT;
    const float* V = g_v + (size_t)bh*TT*HSZ;
    __shared__ float As[16][68];
    __shared__ float Bs[16][64];
    int tid = threadIdx.x, ty = tid>>4, tx = tid&15;
    int arow = tid>>2, akq = (tid&3)*4;
    int brow = tid>>4, bd = (tid&15)*4;
    int kmax = (tb+1)*64;              // P is zero for s > t
    float acc[4][4] = {};
    for(int k0=0;k0<kmax;k0+=16){
        float4 av = *(const float4*)(P + (size_t)(tb*64+arow)*TT + k0 + akq);
        As[akq+0][arow]=av.x; As[akq+1][arow]=av.y; As[akq+2][arow]=av.z; As[akq+3][arow]=av.w;
        *(float4*)&Bs[brow][bd] = *(const float4*)(V + (size_t)(k0+brow)*HSZ + bd);
        __syncthreads();
#pragma unroll
        for(int kk=0;kk<16;kk++){
            float a[4], bb[4];
#pragma unroll
            for(int i=0;i<4;i++) a[i]=As[kk][ty*4+i];
#pragma unroll
            for(int j=0;j<4;j++) bb[j]=Bs[kk][tx*4+j];
#pragma unroll
            for(int i=0;i<4;i++)
#pragma unroll
                for(int j=0;j<4;j++) acc[i][j]+=a[i]*bb[j];
        }
        __syncthreads();
    }
    int b = bh/HH, h = bh%HH;
#pragma unroll
    for(int i=0;i<4;i++)
#pragma unroll
        for(int j=0;j<4;j++)
            g_ao[((size_t)b*TT + tb*64+ty*4+i)*CCH + h*HSZ + tx*4+j] = acc[i][j];
}

// ---------------- generic 128x128x8 SGEMM w/ epilogue options ----------------
// EPI: 0 = bias, 1 = bias+GELU. Optional gather (tok) and dynamic M (cnt),
// optional residual added after epilogue.
template<int EPI>
__global__ void __launch_bounds__(256)
k_gemm128(const float* __restrict__ A, const float* __restrict__ Bm,
          const float* __restrict__ bias, const float* __restrict__ resid,
          float* __restrict__ Co, int M, int Nn, int K,
          const int* __restrict__ tok, const int* __restrict__ cnt){
    if(cnt) M = *cnt;
    int by = blockIdx.y;
    if(by*128 >= M) return;
    int bx = blockIdx.x;
    __shared__ float As[8][132];
    __shared__ float Bs[8][128];
    int tid = threadIdx.x;
    int arow = tid>>1, akq = (tid&1)*4;
    int grow = by*128 + arow;
    bool aval = grow < M;
    int asrc = aval ? (tok ? tok[grow] : grow) : 0;
    const float* Ap = A + (size_t)asrc*K;
    int brow = tid>>5, bcol = (tid&31)*4;
    const float* Bp = Bm + (size_t)brow*Nn + bx*128 + bcol;
    float acc[8][8] = {};
    int rm = (tid>>4)*8, cn = (tid&15)*8;
    for(int k0=0;k0<K;k0+=8){
        float4 av = aval ? *(const float4*)(Ap + k0 + akq) : make_float4(0,0,0,0);
        As[akq+0][arow]=av.x; As[akq+1][arow]=av.y; As[akq+2][arow]=av.z; As[akq+3][arow]=av.w;
        *(float4*)&Bs[brow][bcol] = *(const float4*)(Bp + (size_t)k0*Nn);
        __syncthreads();
#pragma unroll
        for(int kk=0;kk<8;kk++){
            float a[8], bb[8];
            *(float4*)(a  ) = *(const float4*)&As[kk][rm  ];
            *(float4*)(a+4) = *(const float4*)&As[kk][rm+4];
            *(float4*)(bb  ) = *(const float4*)&Bs[kk][cn  ];
            *(float4*)(bb+4) = *(const float4*)&Bs[kk][cn+4];
#pragma unroll
            for(int i=0;i<8;i++)
#pragma unroll
                for(int j=0;j<8;j++) acc[i][j] += a[i]*bb[j];
        }
        __syncthreads();
    }
#pragma unroll
    for(int i=0;i<8;i++){
        int r = by*128+rm+i;
        if(r >= M) break;
        size_t off = (size_t)r*Nn + bx*128+cn;
#pragma unroll
        for(int j=0;j<8;j++){
            float v = acc[i][j] + (bias ? bias[bx*128+cn+j] : 0.f);
            if(EPI==1) v = geluf(v);
            if(resid) v += resid[off+j];
            Co[off+j] = v;
        }
    }
}

// ---------------- noisy top-2 router, builds per-expert token lists ----------------
__global__ void k_router(const float* __restrict__ wr, const float* __restrict__ br,
                         const float* __restrict__ wn, const float* __restrict__ bnn,
                         const float* __restrict__ temp, const float* __restrict__ noise){
    int warp = threadIdx.x>>5, lane = threadIdx.x&31;
    int n = blockIdx.x*8 + warp;
    const float* hp = g_h2 + (size_t)n*CCH;
    float r[8] = {}, q[8] = {};
    for(int c=lane;c<CCH;c+=32){
        float hv = hp[c];
        const float* wrp = wr + c*EE;
        const float* wnp = wn + c*EE;
#pragma unroll
        for(int e=0;e<8;e++){ r[e]+=hv*wrp[e]; q[e]+=hv*wnp[e]; }
    }
#pragma unroll
    for(int e=0;e<8;e++)
#pragma unroll
        for(int o=16;o;o>>=1){
            r[e]+=__shfl_xor_sync(~0u,r[e],o);
            q[e]+=__shfl_xor_sync(~0u,q[e],o);
        }
    if(lane==0){
        float t = fminf(fmaxf(temp[0], 0.5f), 2.0f);
        float noisy[8];
#pragma unroll
        for(int e=0;e<8;e++){
            float lg = r[e]+br[e];
            float z  = q[e]+bnn[e];
            float sp = (z > 20.f) ? z : log1pf(expf(z));
            noisy[e] = lg + t*noise[(size_t)n*EE+e]*sp;
        }
        int i1 = 0;
#pragma unroll
        for(int e=1;e<8;e++) if(noisy[e] > noisy[i1]) i1 = e;
        int i2 = -1;
#pragma unroll
        for(int e=0;e<8;e++){ if(e==i1) continue; if(i2<0 || noisy[e]>noisy[i2]) i2=e; }
        float m = noisy[i1];
        float e2 = expf(noisy[i2]-m);
        float ssum = 1.f + e2;
        float gv[2] = { 1.f/ssum, e2/ssum };
        int   id[2] = { i1, i2 };
#pragma unroll
        for(int k2=0;k2<2;k2++){
            int e = id[k2];
            int row = atomicAdd(&g_cnt[e], 1);
            g_tok[e*NT+row] = n;
            g_pos[n*2+k2]   = e*NT+row;
            g_gw [n*2+k2]   = gv[k2];
        }
    }
}

// ---------------- per-expert residual LayerNorm, scatter to slot buffer ----------------
__global__ void k_resln(const float* __restrict__ t3, int e,
                        const float* __restrict__ gam, const float* __restrict__ bet){
    int r = blockIdx.x;
    if(r >= g_cnt[e]) return;
    int n = g_tok[e*NT + r];
    int t = threadIdx.x;
    float v[3], s=0.f, s2=0.f;
#pragma unroll
    for(int i=0;i<3;i++){
        int c = t+256*i;
        v[i] = g_h2[(size_t)n*CCH+c] + t3[(size_t)r*CCH+c];
        s += v[i]; s2 += v[i]*v[i];
    }
    __shared__ float shs[8], shq[8];
#pragma unroll
    for(int o=16;o;o>>=1){ s+=__shfl_xor_sync(~0u,s,o); s2+=__shfl_xor_sync(~0u,s2,o); }
    if((t&31)==0){ shs[t>>5]=s; shq[t>>5]=s2; }
    __syncthreads();
    s=0.f; s2=0.f;
#pragma unroll
    for(int i=0;i<8;i++){ s+=shs[i]; s2+=shq[i]; }
    float mean = s*(1.f/768.f);
    float var  = s2*(1.f/768.f) - mean*mean;
    float rs = rsqrtf(var + 1e-5f);
    float* ob = g_ob + (size_t)(e*NT + r)*CCH;
#pragma unroll
    for(int i=0;i<3;i++){
        int c = t+256*i;
        ob[c] = (v[i]-mean)*rs*gam[c] + bet[c];
    }
}

// ---------------- final gated combine + residual ----------------
__global__ void k_combine(float* __restrict__ out){
    int n = blockIdx.x, t = threadIdx.x;
    float g0 = g_gw[n*2], g1 = g_gw[n*2+1];
    const float* o0 = g_ob + (size_t)g_pos[n*2  ]*CCH;
    const float* o1 = g_ob + (size_t)g_pos[n*2+1]*CCH;
#pragma unroll
    for(int i=0;i<3;i++){
        int c = t+256*i;
        out[(size_t)n*CCH+c] = g_x2[(size_t)n*CCH+c] + g0*o0[c] + g1*o1[c];
    }
}

// ---------------- host orchestration ----------------
extern "C" void kernel_launch(void* const* d_in, const int* in_sizes, int n_in,
                              void* d_out, int out_size){
    const float* x       = (const float*)d_in[0];
    const float* rnoise  = (const float*)d_in[1];
    const float* wq      = (const float*)d_in[2];
    const float* wk      = (const float*)d_in[3];
    const float* wv      = (const float*)d_in[4];
    const float* w_proj  = (const float*)d_in[5];
    const float* b_proj  = (const float*)d_in[6];
    const float* ln1_g   = (const float*)d_in[7];
    const float* ln1_b   = (const float*)d_in[8];
    const float* ln2_g   = (const float*)d_in[9];
    const float* ln2_b   = (const float*)d_in[10];
    const float* w_route = (const float*)d_in[11];
    const float* b_route = (const float*)d_in[12];
    const float* w_noise = (const float*)d_in[13];
    const float* b_noise = (const float*)d_in[14];
    const float* temp    = (const float*)d_in[15];
    const float* dw1     = (const float*)d_in[16];
    const float* db1     = (const float*)d_in[17];
    const float* dw2     = (const float*)d_in[18];
    const float* db2     = (const float*)d_in[19];
    const float* dw3     = (const float*)d_in[20];
    const float* db3     = (const float*)d_in[21];
    const float* dlng    = (const float*)d_in[22];
    const float* dlnb    = (const float*)d_in[23];
    const float* sw1     = (const float*)d_in[24];
    const float* sb1     = (const float*)d_in[25];
    const float* sw2     = (const float*)d_in[26];
    const float* sb2     = (const float*)d_in[27];
    const float* slng    = (const float*)d_in[28];
    const float* slnb    = (const float*)d_in[29];
    float* out = (float*)d_out;

    // resolve scratch addresses (not allocations)
    float *p_h1, *p_ao, *p_x2, *p_h2, *p_t1, *p_t2, *p_t3;
    int *p_tok, *p_cnt;
    cudaGetSymbolAddress((void**)&p_h1, g_h1);
    cudaGetSymbolAddress((void**)&p_ao, g_ao);
    cudaGetSymbolAddress((void**)&p_x2, g_x2);
    cudaGetSymbolAddress((void**)&p_h2, g_h2);
    cudaGetSymbolAddress((void**)&p_t1, g_t1);
    cudaGetSymbolAddress((void**)&p_t2, g_t2);
    cudaGetSymbolAddress((void**)&p_t3, g_t3);
    cudaGetSymbolAddress((void**)&p_tok, g_tok);
    cudaGetSymbolAddress((void**)&p_cnt, g_cnt);

    k_reset<<<1,32>>>();
    // attention
    k_ln<<<NT,256>>>(x, ln1_g, ln1_b, p_h1);
    k_qkv<<<dim3(TT/64, BH, 3),256>>>(p_h1, wq, wk, wv);
    k_scores<<<dim3(16,16,BH),256>>>();
    k_softmax<<<BH*TT,256>>>();
    k_av<<<dim3(16,BH),256>>>();
    k_gemm128<0><<<dim3(CCH/128, NT/128),256>>>(p_ao, w_proj, b_proj, x, p_x2,
                                                NT, CCH, CCH, nullptr, nullptr);
    // router
    k_ln<<<NT,256>>>(p_x2, ln2_g, ln2_b, p_h2);
    k_router<<<NT/8,256>>>(w_route, b_route, w_noise, b_noise, temp, rnoise);

    // deep experts (0,1): C->F gelu, F->F gelu, F->C, residual LN
    for(int e=0;e<2;e++){
        k_gemm128<1><<<dim3(FF/128, NT/128),256>>>(p_h2, dw1+(size_t)e*CCH*FF, db1+e*FF,
                nullptr, p_t1, NT, FF, CCH, p_tok+e*NT, p_cnt+e);
        k_gemm128<1><<<dim3(FF/128, NT/128),256>>>(p_t1, dw2+(size_t)e*FF*FF, db2+e*FF,
                nullptr, p_t2, NT, FF, FF, nullptr, p_cnt+e);
        k_gemm128<0><<<dim3(CCH/128, NT/128),256>>>(p_t2, dw3+(size_t)e*FF*CCH, db3+e*CCH,
                nullptr, p_t3, NT, CCH, FF, nullptr, p_cnt+e);
        k_resln<<<NT,256>>>(p_t3, e, dlng+e*CCH, dlnb+e*CCH);
    }
    // simple experts (2..7): C->F gelu, F->C, residual LN
    for(int e=0;e<6;e++){
        int ge = 2+e;
        k_gemm128<1><<<dim3(FF/128, NT/128),256>>>(p_h2, sw1+(size_t)e*CCH*FF, sb1+e*FF,
                nullptr, p_t1, NT, FF, CCH, p_tok+ge*NT, p_cnt+ge);
        k_gemm128<0><<<dim3(CCH/128, NT/128),256>>>(p_t1, sw2+(size_t)e*FF*CCH, sb2+e*CCH,
                nullptr, p_t3, NT, CCH, FF, nullptr, p_cnt+ge);
        k_resln<<<NT,256>>>(p_t3, ge, slng+e*CCH, slnb+e*CCH);
    }
    // combine
    k_combine<<<NT,256>>>(out);
}